// round 3
// baseline (speedup 1.0000x reference)
#include <cuda_runtime.h>

#define NQ     10
#define NGEN   4
#define QDEPTH 6

// State layout: one warp per circuit. Amplitude index i = (lane<<5) | k,
// lane = bits 9..5, register index k = bits 4..0.
// Wire q (PennyLane: wire 0 = most significant) acts on bit P = NQ-1-q.

template<int P>
__device__ __forceinline__ void ry_gate(float (&ar)[32], float (&ai)[32],
                                        float c, float s, unsigned lane) {
    if constexpr (P < 5) {
        constexpr int m = 1 << P;
        #pragma unroll
        for (int k = 0; k < 32; ++k) {
            if ((k & m) == 0) {
                const int j = k | m;
                float a0r = ar[k], a1r = ar[j];
                float a0i = ai[k], a1i = ai[j];
                ar[k] = fmaf(-s, a1r, c * a0r);
                ar[j] = fmaf( s, a0r, c * a1r);
                ai[k] = fmaf(-s, a1i, c * a0i);
                ai[j] = fmaf( s, a0i, c * a1i);
            }
        }
    } else {
        constexpr int lm = 1 << (P - 5);
        const float t = (lane & (unsigned)lm) ? s : -s;
        #pragma unroll
        for (int k = 0; k < 32; ++k) {
            float br = __shfl_xor_sync(0xffffffffu, ar[k], lm);
            float bi = __shfl_xor_sync(0xffffffffu, ai[k], lm);
            ar[k] = fmaf(t, br, c * ar[k]);
            ai[k] = fmaf(t, bi, c * ai[k]);
        }
    }
}

template<int P>
__device__ __forceinline__ void rx_gate(float (&ar)[32], float (&ai)[32],
                                        float c, float s, unsigned lane) {
    if constexpr (P < 5) {
        constexpr int m = 1 << P;
        #pragma unroll
        for (int k = 0; k < 32; ++k) {
            if ((k & m) == 0) {
                const int j = k | m;
                float a0r = ar[k], a0i = ai[k];
                float a1r = ar[j], a1i = ai[j];
                ar[k] = fmaf( s, a1i, c * a0r);
                ai[k] = fmaf(-s, a1r, c * a0i);
                ar[j] = fmaf( s, a0i, c * a1r);
                ai[j] = fmaf(-s, a0r, c * a1i);
            }
        }
    } else {
        constexpr int lm = 1 << (P - 5);
        // RX across lanes: new_r = c*ar + s*bi ; new_i = c*ai - s*br  (same both sides)
        #pragma unroll
        for (int k = 0; k < 32; ++k) {
            float br = __shfl_xor_sync(0xffffffffu, ar[k], lm);
            float bi = __shfl_xor_sync(0xffffffffu, ai[k], lm);
            ar[k] = fmaf( s, bi, c * ar[k]);
            ai[k] = fmaf(-s, br, c * ai[k]);
        }
    }
}

template<int P>
__device__ __forceinline__ float expect_x(const float (&ar)[32], const float (&ai)[32]) {
    float acc = 0.0f;
    if constexpr (P < 5) {
        constexpr int m = 1 << P;
        #pragma unroll
        for (int k = 0; k < 32; ++k) {
            acc = fmaf(ar[k], ar[k ^ m], acc);
            acc = fmaf(ai[k], ai[k ^ m], acc);
        }
    } else {
        constexpr int lm = 1 << (P - 5);
        #pragma unroll
        for (int k = 0; k < 32; ++k) {
            float br = __shfl_xor_sync(0xffffffffu, ar[k], lm);
            float bi = __shfl_xor_sync(0xffffffffu, ai[k], lm);
            acc = fmaf(ar[k], br, acc);
            acc = fmaf(ai[k], bi, acc);
        }
    }
    #pragma unroll
    for (int o = 16; o; o >>= 1)
        acc += __shfl_xor_sync(0xffffffffu, acc, o);
    return acc;
}

__global__ void __launch_bounds__(256)
qgen_kernel(const float* __restrict__ noise,
            const float* __restrict__ qp,
            float* __restrict__ out,
            int batch)
{
    const unsigned lane = threadIdx.x & 31u;
    const unsigned wid  = blockIdx.x * (blockDim.x >> 5) + (threadIdx.x >> 5);
    const unsigned g = wid / (unsigned)batch;
    const unsigned b = wid % (unsigned)batch;
    if (g >= NGEN) return;

    // CZ-chain sign mask: bit k set iff parity of adjacent 1-1 bit pairs of
    // index i = (lane<<5)|k is odd.
    unsigned sgn = 0u;
    #pragma unroll
    for (int k = 0; k < 32; ++k) {
        unsigned i = (lane << 5) | (unsigned)k;
        sgn |= ((unsigned)(__popc(i & (i >> 1)) & 1)) << k;
    }

    float ar[32], ai[32];
    #pragma unroll
    for (int k = 0; k < 32; ++k) { ar[k] = 0.0f; ai[k] = 0.0f; }
    ar[0] = (lane == 0) ? 1.0f : 0.0f;

    // ---- init: RY(noise_q) then RX(noise_q) on each wire q ----
    const float* nb = noise + (size_t)b * NQ;
    #define INITQ(q) { float c, s; __sincosf(0.5f * nb[q], &s, &c); \
                       ry_gate<NQ - 1 - (q)>(ar, ai, c, s, lane); \
                       rx_gate<NQ - 1 - (q)>(ar, ai, c, s, lane); }
    INITQ(0) INITQ(1) INITQ(2) INITQ(3) INITQ(4)
    INITQ(5) INITQ(6) INITQ(7) INITQ(8) INITQ(9)
    #undef INITQ

    // ---- layers: RY(w[l][q]) on each wire, then CZ-chain diagonal ----
    const float* wg = qp + (size_t)g * (QDEPTH * NQ);
    for (int l = 0; l < QDEPTH; ++l) {
        const float* wl = wg + l * NQ;
        #define LQ(q) { float c, s; __sincosf(0.5f * wl[q], &s, &c); \
                        ry_gate<NQ - 1 - (q)>(ar, ai, c, s, lane); }
        LQ(0) LQ(1) LQ(2) LQ(3) LQ(4) LQ(5) LQ(6) LQ(7) LQ(8) LQ(9)
        #undef LQ
        #pragma unroll
        for (int k = 0; k < 32; ++k) {
            unsigned x = ((sgn >> k) & 1u) << 31;
            ar[k] = __uint_as_float(__float_as_uint(ar[k]) ^ x);
            ai[k] = __uint_as_float(__float_as_uint(ai[k]) ^ x);
        }
    }

    // ---- expectations <X_q>, output layout out[b, g*NQ + q] ----
    float* ob = out + (size_t)b * (NGEN * NQ) + (size_t)g * NQ;
    #define EXQ(q) { float e = expect_x<NQ - 1 - (q)>(ar, ai); \
                     if (lane == 0) ob[q] = e; }
    EXQ(0) EXQ(1) EXQ(2) EXQ(3) EXQ(4)
    EXQ(5) EXQ(6) EXQ(7) EXQ(8) EXQ(9)
    #undef EXQ
}

extern "C" void kernel_launch(void* const* d_in, const int* in_sizes, int n_in,
                              void* d_out, int out_size) {
    const float* noise = (const float*)d_in[0];   // (BATCH, NQ) fp32
    const float* qp    = (const float*)d_in[1];   // (NGEN, QDEPTH, NQ) fp32
    float* out = (float*)d_out;                   // (BATCH, NGEN*NQ) fp32

    int batch   = in_sizes[0] / NQ;
    int warps   = NGEN * batch;
    int threads = 256;
    int blocks  = (warps * 32 + threads - 1) / threads;
    qgen_kernel<<<blocks, threads>>>(noise, qp, out, batch);
}

// round 4
// speedup vs baseline: 1.1899x; 1.1899x over previous
#include <cuda_runtime.h>

typedef unsigned long long u64;

#define NQ     10
#define NGEN   4
#define QDEPTH 6
#define WPB    2   // warps per block

// Parity-of-adjacent-pairs mask for 5-bit k: bit k = popc(k & (k>>1)) & 1.
// Verified by hand: set bits {3,6,11,12,13,15,19,22,24,25,26,30}.
#define MK_CONST 0x4748B848u

constexpr unsigned mk_check() {
    unsigned m = 0;
    for (int k = 0; k < 32; ++k) {
        int p = 0;
        for (int bb = 0; bb < 4; ++bb) p ^= ((k >> bb) & 1) & ((k >> (bb + 1)) & 1);
        m |= (unsigned)p << k;
    }
    return m;
}
static_assert(mk_check() == MK_CONST, "MK mask mismatch");

// ---- packed f32x2 helpers (SASS FFMA2 — PTX-only on sm_103a) ----
__device__ __forceinline__ u64 fma2(u64 a, u64 b, u64 c) {
    u64 d; asm("fma.rn.f32x2 %0, %1, %2, %3;" : "=l"(d) : "l"(a), "l"(b), "l"(c)); return d;
}
__device__ __forceinline__ u64 mul2(u64 a, u64 b) {
    u64 d; asm("mul.rn.f32x2 %0, %1, %2;" : "=l"(d) : "l"(a), "l"(b)); return d;
}
__device__ __forceinline__ u64 pack2(float lo, float hi) {
    u64 d; asm("mov.b64 %0, {%1, %2};" : "=l"(d) : "f"(lo), "f"(hi)); return d;
}
__device__ __forceinline__ void unpack2(u64 v, float& lo, float& hi) {
    asm("mov.b64 {%0, %1}, %2;" : "=f"(lo), "=f"(hi) : "l"(v));
}

// ---- gates: all register-local butterflies on packed (re,im) amplitudes ----
template<int M>
__device__ __forceinline__ void ry2(u64 (&v)[32], float c, float s) {
    const u64 cc = pack2(c, c), ss = pack2(s, s), ns = pack2(-s, -s);
    #pragma unroll
    for (int k = 0; k < 32; ++k) if (!(k & M)) {
        const int j = k | M;
        u64 a0 = v[k], a1 = v[j];
        v[k] = fma2(ns, a1, mul2(cc, a0));   // c*a0 - s*a1  (re & im)
        v[j] = fma2(ss, a0, mul2(cc, a1));   // c*a1 + s*a0
    }
}

template<int M>
__device__ __forceinline__ void rx2(u64 (&v)[32], float c, float s) {
    #pragma unroll
    for (int k = 0; k < 32; ++k) if (!(k & M)) {
        const int j = k | M;
        float a0r, a0i, a1r, a1i;
        unpack2(v[k], a0r, a0i);
        unpack2(v[j], a1r, a1i);
        v[k] = pack2(fmaf(s, a1i, c * a0r), fmaf(-s, a1r, c * a0i));
        v[j] = pack2(fmaf(s, a0i, c * a1r), fmaf(-s, a0r, c * a1i));
    }
}

// <X> on a register wire: sum_i a_i * a_{i^M}  (re and im parts accumulate in the two lanes)
template<int M>
__device__ __forceinline__ float exv(const u64 (&v)[32]) {
    u64 acc0 = 0ull, acc1 = 0ull, acc2 = 0ull, acc3 = 0ull;
    #pragma unroll
    for (int k = 0; k < 32; k += 4) {
        acc0 = fma2(v[k + 0], v[(k + 0) ^ M], acc0);
        acc1 = fma2(v[k + 1], v[(k + 1) ^ M], acc1);
        acc2 = fma2(v[k + 2], v[(k + 2) ^ M], acc2);
        acc3 = fma2(v[k + 3], v[(k + 3) ^ M], acc3);
    }
    float l0, h0, l1, h1, l2, h2, l3, h3;
    unpack2(acc0, l0, h0); unpack2(acc1, l1, h1);
    unpack2(acc2, l2, h2); unpack2(acc3, l3, h3);
    return (l0 + h0) + (l1 + h1) + ((l2 + h2) + (l3 + h3));
}

// CZ-chain diagonal: flip sign (both re & im) where mask bit set
__device__ __forceinline__ void cz_apply(u64 (&v)[32], unsigned sgn) {
    #pragma unroll
    for (int k = 0; k < 32; ++k)
        v[k] ^= (sgn & (1u << k)) ? 0x8000000080000000ull : 0ull;
}

// 32x32 warp transpose of packed amplitudes through padded smem (stride 34
// u64 rows: STS.128 writes conflict-free, LDS.64 column reads conflict-free).
// Swaps which 5 global index bits live in the lane id vs the register index.
__device__ __forceinline__ void transpose(u64 (&v)[32], u64* t, unsigned lane) {
    __syncwarp();
    #pragma unroll
    for (int r = 0; r < 32; r += 2)
        *reinterpret_cast<ulonglong2*>(t + lane * 34u + r) = make_ulonglong2(v[r], v[r + 1]);
    __syncwarp();
    #pragma unroll
    for (int k = 0; k < 32; ++k)
        v[k] = t[k * 34u + lane];
}

// 5 RY gates on the register half (wire order maps to M = 16,8,4,2,1 in both layouts)
__device__ __forceinline__ void half_ry(u64 (&v)[32], const float* __restrict__ a) {
    float c, s;
    __sincosf(0.5f * a[0], &s, &c); ry2<16>(v, c, s);
    __sincosf(0.5f * a[1], &s, &c); ry2<8>(v, c, s);
    __sincosf(0.5f * a[2], &s, &c); ry2<4>(v, c, s);
    __sincosf(0.5f * a[3], &s, &c); ry2<2>(v, c, s);
    __sincosf(0.5f * a[4], &s, &c); ry2<1>(v, c, s);
}

__device__ __forceinline__ void half_ryrx(u64 (&v)[32], const float* __restrict__ a) {
    float c, s;
    __sincosf(0.5f * a[0], &s, &c); ry2<16>(v, c, s); rx2<16>(v, c, s);
    __sincosf(0.5f * a[1], &s, &c); ry2<8>(v, c, s);  rx2<8>(v, c, s);
    __sincosf(0.5f * a[2], &s, &c); ry2<4>(v, c, s);  rx2<4>(v, c, s);
    __sincosf(0.5f * a[3], &s, &c); ry2<2>(v, c, s);  rx2<2>(v, c, s);
    __sincosf(0.5f * a[4], &s, &c); ry2<1>(v, c, s);  rx2<1>(v, c, s);
}

// One warp per batch sample; computes the 20 shared init gates once, snapshots
// the state, then replays the 4 generator tails.
// Layout A: global index i = lane*32 + k  (register wires 5..9)
// Layout B: global index i = k*32 + lane  (register wires 0..4)
__global__ void __launch_bounds__(32 * WPB)
qgen_kernel(const float* __restrict__ noise,
            const float* __restrict__ qp,
            float* __restrict__ out, int batch)
{
    __shared__ u64 tile[WPB][32 * 34];
    __shared__ u64 snap[WPB][32 * 34];

    const unsigned lane = threadIdx.x & 31u;
    const unsigned w    = threadIdx.x >> 5;
    const unsigned b    = blockIdx.x * WPB + w;
    if ((int)b >= batch) return;
    u64* t  = tile[w];
    u64* sp = snap[w];

    // CZ sign masks. Parity(i & i>>1) decomposes into: pairs within the k-bits
    // (MK), pairs within the lane-bits (pL), and the boundary pair.
    const unsigned pL   = (__popc(lane & (lane >> 1)) & 1) ? 0xFFFFFFFFu : 0u;
    const unsigned sgnA = MK_CONST ^ pL ^ ((lane & 1u)        ? 0xFFFF0000u : 0u); // i = lane<<5 | k
    const unsigned sgnB = MK_CONST ^ pL ^ (((lane >> 4) & 1u) ? 0xAAAAAAAAu : 0u); // i = k<<5 | lane

    u64 v[32];
    #pragma unroll
    for (int k = 0; k < 32; ++k) v[k] = 0ull;
    if (lane == 0) v[0] = pack2(1.0f, 0.0f);

    // ---- init (shared across generators): RY(n)+RX(n) on every wire ----
    const float* nb = noise + (size_t)b * NQ;
    half_ryrx(v, nb + 5);        // layout A: wires 5..9
    transpose(v, t, lane);       // -> layout B
    half_ryrx(v, nb + 0);        // wires 0..4

    // snapshot (layout B); per-lane rows, each lane reads back only its own row
    #pragma unroll
    for (int r = 0; r < 32; r += 2)
        *reinterpret_cast<ulonglong2*>(sp + lane * 34u + r) = make_ulonglong2(v[r], v[r + 1]);

    float* ob = out + (size_t)b * (NGEN * NQ);

    for (int g = 0; g < NGEN; ++g) {
        if (g) {
            #pragma unroll
            for (int k = 0; k < 32; ++k) v[k] = sp[lane * 34u + k];
        }
        const float* wg = qp + g * (QDEPTH * NQ);

        // layers alternate starting layout: B, A, B, A, B, A  (end in B)
        #pragma unroll
        for (int l = 0; l < QDEPTH; l += 2) {
            const float* w0 = wg + l * NQ;
            half_ry(v, w0 + 0);        // layout B: wires 0..4
            transpose(v, t, lane);     // -> A
            half_ry(v, w0 + 5);        // wires 5..9
            cz_apply(v, sgnA);
            const float* w1 = w0 + NQ;
            half_ry(v, w1 + 5);        // layout A: wires 5..9
            transpose(v, t, lane);     // -> B
            half_ry(v, w1 + 0);        // wires 0..4
            cz_apply(v, sgnB);
        }

        // ---- expectations ----
        float e[10];
        e[0] = exv<16>(v); e[1] = exv<8>(v); e[2] = exv<4>(v);   // layout B: wires 0..4
        e[3] = exv<2>(v);  e[4] = exv<1>(v);
        transpose(v, t, lane);                                   // -> A
        e[5] = exv<16>(v); e[6] = exv<8>(v); e[7] = exv<4>(v);   // wires 5..9
        e[8] = exv<2>(v);  e[9] = exv<1>(v);

        #pragma unroll
        for (int q = 0; q < 10; ++q) {
            float a = e[q];
            #pragma unroll
            for (int o = 16; o; o >>= 1) a += __shfl_xor_sync(0xffffffffu, a, o);
            e[q] = a;
        }
        if (lane == 0) {
            #pragma unroll
            for (int q = 0; q < 10; ++q) ob[g * NQ + q] = e[q];
        }
    }
}

extern "C" void kernel_launch(void* const* d_in, const int* in_sizes, int n_in,
                              void* d_out, int out_size) {
    const float* noise = (const float*)d_in[0];   // (BATCH, NQ) fp32
    const float* qp    = (const float*)d_in[1];   // (NGEN, QDEPTH, NQ) fp32
    float* out = (float*)d_out;                   // (BATCH, NGEN*NQ) fp32

    int batch  = in_sizes[0] / NQ;
    int blocks = (batch + WPB - 1) / WPB;
    qgen_kernel<<<blocks, 32 * WPB>>>(noise, qp, out, batch);
}

// round 5
// speedup vs baseline: 1.2430x; 1.0446x over previous
#include <cuda_runtime.h>

typedef unsigned long long u64;

#define NQ     10
#define NGEN   4
#define QDEPTH 6
#define MAXB   1024
#define WPB    4   // warps per block

// Parity-of-adjacent-pairs mask for 5-bit k: bit k = popc(k & (k>>1)) & 1.
#define MK_CONST 0x4748B848u
constexpr unsigned mk_check() {
    unsigned m = 0;
    for (int k = 0; k < 32; ++k) {
        int p = 0;
        for (int bb = 0; bb < 4; ++bb) p ^= ((k >> bb) & 1) & ((k >> (bb + 1)) & 1);
        m |= (unsigned)p << k;
    }
    return m;
}
static_assert(mk_check() == MK_CONST, "MK mask mismatch");

// 8 MB inter-kernel scratch: snapshot state per batch sample, layout B
// (global index i = k*32 + lane, stored at snap[b*1024 + i]).
__device__ u64 g_snap[MAXB * 1024];

// ---- packed f32x2 helpers (SASS FFMA2 — PTX-only on sm_103a) ----
__device__ __forceinline__ u64 fma2(u64 a, u64 b, u64 c) {
    u64 d; asm("fma.rn.f32x2 %0, %1, %2, %3;" : "=l"(d) : "l"(a), "l"(b), "l"(c)); return d;
}
__device__ __forceinline__ u64 mul2(u64 a, u64 b) {
    u64 d; asm("mul.rn.f32x2 %0, %1, %2;" : "=l"(d) : "l"(a), "l"(b)); return d;
}
__device__ __forceinline__ u64 pack2(float lo, float hi) {
    u64 d; asm("mov.b64 %0, {%1, %2};" : "=l"(d) : "f"(lo), "f"(hi)); return d;
}
__device__ __forceinline__ void unpack2(u64 v, float& lo, float& hi) {
    asm("mov.b64 {%0, %1}, %2;" : "=f"(lo), "=f"(hi) : "l"(v));
}

// ---- gates: register-local butterflies on packed (re,im) amplitudes ----
template<int M>
__device__ __forceinline__ void ry2(u64 (&v)[32], float c, float s) {
    const u64 cc = pack2(c, c), ss = pack2(s, s), ns = pack2(-s, -s);
    #pragma unroll
    for (int k = 0; k < 32; ++k) if (!(k & M)) {
        const int j = k | M;
        u64 a0 = v[k], a1 = v[j];
        v[k] = fma2(ns, a1, mul2(cc, a0));   // c*a0 - s*a1
        v[j] = fma2(ss, a0, mul2(cc, a1));   // c*a1 + s*a0
    }
}

template<int M>
__device__ __forceinline__ void rx2(u64 (&v)[32], float c, float s) {
    #pragma unroll
    for (int k = 0; k < 32; ++k) if (!(k & M)) {
        const int j = k | M;
        float a0r, a0i, a1r, a1i;
        unpack2(v[k], a0r, a0i);
        unpack2(v[j], a1r, a1i);
        v[k] = pack2(fmaf(s, a1i, c * a0r), fmaf(-s, a1r, c * a0i));
        v[j] = pack2(fmaf(s, a0i, c * a1r), fmaf(-s, a0r, c * a1i));
    }
}

template<int M>
__device__ __forceinline__ float exv(const u64 (&v)[32]) {
    u64 acc0 = 0ull, acc1 = 0ull, acc2 = 0ull, acc3 = 0ull;
    #pragma unroll
    for (int k = 0; k < 32; k += 4) {
        acc0 = fma2(v[k + 0], v[(k + 0) ^ M], acc0);
        acc1 = fma2(v[k + 1], v[(k + 1) ^ M], acc1);
        acc2 = fma2(v[k + 2], v[(k + 2) ^ M], acc2);
        acc3 = fma2(v[k + 3], v[(k + 3) ^ M], acc3);
    }
    float l0, h0, l1, h1, l2, h2, l3, h3;
    unpack2(acc0, l0, h0); unpack2(acc1, l1, h1);
    unpack2(acc2, l2, h2); unpack2(acc3, l3, h3);
    return (l0 + h0) + (l1 + h1) + ((l2 + h2) + (l3 + h3));
}

__device__ __forceinline__ void cz_apply(u64 (&v)[32], unsigned sgn) {
    #pragma unroll
    for (int k = 0; k < 32; ++k)
        v[k] ^= (sgn & (1u << k)) ? 0x8000000080000000ull : 0ull;
}

// 32x32 warp transpose through padded smem (stride-34 u64 rows: conflict-free).
__device__ __forceinline__ void transpose(u64 (&v)[32], u64* t, unsigned lane) {
    __syncwarp();
    #pragma unroll
    for (int r = 0; r < 32; r += 2)
        *reinterpret_cast<ulonglong2*>(t + lane * 34u + r) = make_ulonglong2(v[r], v[r + 1]);
    __syncwarp();
    #pragma unroll
    for (int k = 0; k < 32; ++k)
        v[k] = t[k * 34u + lane];
}

__device__ __forceinline__ void half_ry(u64 (&v)[32], const float* __restrict__ a) {
    float c, s;
    __sincosf(0.5f * a[0], &s, &c); ry2<16>(v, c, s);
    __sincosf(0.5f * a[1], &s, &c); ry2<8>(v, c, s);
    __sincosf(0.5f * a[2], &s, &c); ry2<4>(v, c, s);
    __sincosf(0.5f * a[3], &s, &c); ry2<2>(v, c, s);
    __sincosf(0.5f * a[4], &s, &c); ry2<1>(v, c, s);
}

__device__ __forceinline__ void half_ryrx(u64 (&v)[32], const float* __restrict__ a) {
    float c, s;
    __sincosf(0.5f * a[0], &s, &c); ry2<16>(v, c, s); rx2<16>(v, c, s);
    __sincosf(0.5f * a[1], &s, &c); ry2<8>(v, c, s);  rx2<8>(v, c, s);
    __sincosf(0.5f * a[2], &s, &c); ry2<4>(v, c, s);  rx2<4>(v, c, s);
    __sincosf(0.5f * a[3], &s, &c); ry2<2>(v, c, s);  rx2<2>(v, c, s);
    __sincosf(0.5f * a[4], &s, &c); ry2<1>(v, c, s);  rx2<1>(v, c, s);
}

// ===== Kernel 1: shared init (one warp per batch sample) =====
// Layout A: i = lane*32 + k ; Layout B: i = k*32 + lane.
__global__ void __launch_bounds__(32 * WPB)
qgen_init(const float* __restrict__ noise, int batch)
{
    __shared__ u64 tile[WPB][32 * 34];
    const unsigned lane = threadIdx.x & 31u;
    const unsigned w    = threadIdx.x >> 5;
    const unsigned b    = blockIdx.x * WPB + w;
    if ((int)b >= batch) return;

    u64 v[32];
    #pragma unroll
    for (int k = 0; k < 32; ++k) v[k] = 0ull;
    if (lane == 0) v[0] = pack2(1.0f, 0.0f);

    const float* nb = noise + (size_t)b * NQ;
    half_ryrx(v, nb + 5);              // layout A: wires 5..9
    transpose(v, tile[w], lane);       // -> layout B
    half_ryrx(v, nb + 0);              // wires 0..4

    u64* sp = g_snap + (size_t)b * 1024;
    #pragma unroll
    for (int k = 0; k < 32; ++k)
        sp[k * 32 + lane] = v[k];      // coalesced STG.64
}

// ===== Kernel 2: generator tails (one warp per (b, g)) =====
__global__ void __launch_bounds__(32 * WPB)
qgen_tail(const float* __restrict__ qp,
          float* __restrict__ out, int batch)
{
    __shared__ u64 tile[WPB][32 * 34];
    const unsigned lane = threadIdx.x & 31u;
    const unsigned w    = threadIdx.x >> 5;
    const unsigned wid  = blockIdx.x * WPB + w;
    const unsigned b    = wid >> 2;          // 4 gens of one sample share a block
    const unsigned g    = wid & 3u;
    if ((int)b >= batch) return;
    u64* t = tile[w];

    const unsigned pL   = (__popc(lane & (lane >> 1)) & 1) ? 0xFFFFFFFFu : 0u;
    const unsigned sgnA = MK_CONST ^ pL ^ ((lane & 1u)        ? 0xFFFF0000u : 0u);
    const unsigned sgnB = MK_CONST ^ pL ^ (((lane >> 4) & 1u) ? 0xAAAAAAAAu : 0u);

    // load snapshot (layout B); coalesced, L1-shared across the block's 4 warps
    u64 v[32];
    const u64* sp = g_snap + (size_t)b * 1024;
    #pragma unroll
    for (int k = 0; k < 32; ++k)
        v[k] = sp[k * 32 + lane];

    const float* wg = qp + g * (QDEPTH * NQ);
    #pragma unroll
    for (int l = 0; l < QDEPTH; l += 2) {
        const float* w0 = wg + l * NQ;
        half_ry(v, w0 + 0);        // layout B: wires 0..4
        transpose(v, t, lane);     // -> A
        half_ry(v, w0 + 5);        // wires 5..9
        cz_apply(v, sgnA);
        const float* w1 = w0 + NQ;
        half_ry(v, w1 + 5);        // layout A: wires 5..9
        transpose(v, t, lane);     // -> B
        half_ry(v, w1 + 0);        // wires 0..4
        cz_apply(v, sgnB);
    }

    float e[10];
    e[0] = exv<16>(v); e[1] = exv<8>(v); e[2] = exv<4>(v);   // layout B: wires 0..4
    e[3] = exv<2>(v);  e[4] = exv<1>(v);
    transpose(v, t, lane);                                    // -> A
    e[5] = exv<16>(v); e[6] = exv<8>(v); e[7] = exv<4>(v);   // wires 5..9
    e[8] = exv<2>(v);  e[9] = exv<1>(v);

    #pragma unroll
    for (int q = 0; q < 10; ++q) {
        float a = e[q];
        #pragma unroll
        for (int o = 16; o; o >>= 1) a += __shfl_xor_sync(0xffffffffu, a, o);
        e[q] = a;
    }
    if (lane == 0) {
        float* ob = out + (size_t)b * (NGEN * NQ) + (size_t)g * NQ;
        #pragma unroll
        for (int q = 0; q < 10; ++q) ob[q] = e[q];
    }
}

extern "C" void kernel_launch(void* const* d_in, const int* in_sizes, int n_in,
                              void* d_out, int out_size) {
    const float* noise = (const float*)d_in[0];   // (BATCH, NQ) fp32
    const float* qp    = (const float*)d_in[1];   // (NGEN, QDEPTH, NQ) fp32
    float* out = (float*)d_out;                   // (BATCH, NGEN*NQ) fp32

    int batch = in_sizes[0] / NQ;
    if (batch > MAXB) batch = MAXB;

    int init_blocks = (batch + WPB - 1) / WPB;
    qgen_init<<<init_blocks, 32 * WPB>>>(noise, batch);

    int tail_warps  = batch * NGEN;
    int tail_blocks = (tail_warps + WPB - 1) / WPB;
    qgen_tail<<<tail_blocks, 32 * WPB>>>(qp, out, batch);
}

// round 8
// speedup vs baseline: 1.3349x; 1.0739x over previous
#include <cuda_runtime.h>

typedef unsigned long long u64;

#define NQ     10
#define NGEN   4
#define QDEPTH 6
#define MAXB   1024
#define WPB    4   // warps per block

// Parity-of-adjacent-pairs mask for 5-bit k: bit k = popc(k & (k>>1)) & 1.
#define MK_CONST 0x4748B848u
constexpr unsigned mk_check() {
    unsigned m = 0;
    for (int k = 0; k < 32; ++k) {
        int p = 0;
        for (int bb = 0; bb < 4; ++bb) p ^= ((k >> bb) & 1) & ((k >> (bb + 1)) & 1);
        m |= (unsigned)p << k;
    }
    return m;
}
static_assert(mk_check() == MK_CONST, "MK mask mismatch");

// 8 MB inter-kernel scratch: snapshot state per batch sample, layout B
// (global index i = k*32 + lane, stored at snap[b*1024 + i]).
__device__ u64 g_snap[MAXB * 1024];

// ---- packed f32x2 helpers (SASS FFMA2 — PTX-only on sm_103a) ----
__device__ __forceinline__ u64 fma2(u64 a, u64 b, u64 c) {
    u64 d; asm("fma.rn.f32x2 %0, %1, %2, %3;" : "=l"(d) : "l"(a), "l"(b), "l"(c)); return d;
}
__device__ __forceinline__ u64 mul2(u64 a, u64 b) {
    u64 d; asm("mul.rn.f32x2 %0, %1, %2;" : "=l"(d) : "l"(a), "l"(b)); return d;
}
__device__ __forceinline__ u64 pack2(float lo, float hi) {
    u64 d; asm("mov.b64 %0, {%1, %2};" : "=l"(d) : "f"(lo), "f"(hi)); return d;
}
__device__ __forceinline__ void unpack2(u64 v, float& lo, float& hi) {
    asm("mov.b64 {%0, %1}, %2;" : "=f"(lo), "=f"(hi) : "l"(v));
}

// ---- RY via 4-op form (used in init; safe for any angle) ----
// c = cos(phi), s = sin(phi) where phi is the rotation angle.
template<int M>
__device__ __forceinline__ void ry2(u64 (&v)[32], float c, float s) {
    const u64 cc = pack2(c, c), ss = pack2(s, s), ns = pack2(-s, -s);
    #pragma unroll
    for (int k = 0; k < 32; ++k) if (!(k & M)) {
        const int j = k | M;
        u64 a0 = v[k], a1 = v[j];
        v[k] = fma2(ns, a1, mul2(cc, a0));   // c*a0 - s*a1
        v[j] = fma2(ss, a0, mul2(cc, a1));   // c*a1 + s*a0
    }
}

// ---- RY via shear/lifting: 3 FMA per pair.
// Rotation by phi: nt = -tan(phi/2), sn = sin(phi).
// x' = x + nt*y ; y' = y + sn*x' ; x'' = x' + nt*y'  ==  [c,-s; s,c]
template<int M>
__device__ __forceinline__ void ry2_shear(u64 (&v)[32], u64 nt, u64 sn) {
    #pragma unroll
    for (int k = 0; k < 32; ++k) if (!(k & M)) {
        const int j = k | M;
        u64 a0 = v[k], a1 = v[j];
        a0 = fma2(nt, a1, a0);
        a1 = fma2(sn, a0, a1);
        a0 = fma2(nt, a1, a0);
        v[k] = a0; v[j] = a1;
    }
}

template<int M>
__device__ __forceinline__ void rx2(u64 (&v)[32], float c, float s) {
    #pragma unroll
    for (int k = 0; k < 32; ++k) if (!(k & M)) {
        const int j = k | M;
        float a0r, a0i, a1r, a1i;
        unpack2(v[k], a0r, a0i);
        unpack2(v[j], a1r, a1i);
        v[k] = pack2(fmaf(s, a1i, c * a0r), fmaf(-s, a1r, c * a0i));
        v[j] = pack2(fmaf(s, a0i, c * a1r), fmaf(-s, a0r, c * a1i));
    }
}

template<int M>
__device__ __forceinline__ float exv(const u64 (&v)[32]) {
    u64 acc0 = 0ull, acc1 = 0ull, acc2 = 0ull, acc3 = 0ull;
    #pragma unroll
    for (int k = 0; k < 32; k += 4) {
        acc0 = fma2(v[k + 0], v[(k + 0) ^ M], acc0);
        acc1 = fma2(v[k + 1], v[(k + 1) ^ M], acc1);
        acc2 = fma2(v[k + 2], v[(k + 2) ^ M], acc2);
        acc3 = fma2(v[k + 3], v[(k + 3) ^ M], acc3);
    }
    float l0, h0, l1, h1, l2, h2, l3, h3;
    unpack2(acc0, l0, h0); unpack2(acc1, l1, h1);
    unpack2(acc2, l2, h2); unpack2(acc3, l3, h3);
    return (l0 + h0) + (l1 + h1) + ((l2 + h2) + (l3 + h3));
}

__device__ __forceinline__ void cz_apply(u64 (&v)[32], unsigned sgn) {
    #pragma unroll
    for (int k = 0; k < 32; ++k)
        v[k] ^= (sgn & (1u << k)) ? 0x8000000080000000ull : 0ull;
}

// 32x32 warp transpose through padded smem (stride-34 u64 rows: conflict-free).
__device__ __forceinline__ void transpose(u64 (&v)[32], u64* t, unsigned lane) {
    __syncwarp();
    #pragma unroll
    for (int r = 0; r < 32; r += 2)
        *reinterpret_cast<ulonglong2*>(t + lane * 34u + r) = make_ulonglong2(v[r], v[r + 1]);
    __syncwarp();
    #pragma unroll
    for (int k = 0; k < 32; ++k)
        v[k] = t[k * 34u + lane];
}

// shear constants for RY(theta): rotation angle phi = theta/2.
// nt = -tan(phi/2) = -tan(theta/4);  sn = sin(phi) = 2*sin(theta/4)*cos(theta/4)
__device__ __forceinline__ void shear_consts(float th, u64& nt, u64& sn) {
    float s4, c4;
    __sincosf(0.25f * th, &s4, &c4);
    float t = -__fdividef(s4, c4);
    float s = 2.0f * s4 * c4;
    nt = pack2(t, t);
    sn = pack2(s, s);
}

// 5 shear-RY gates on the register half (wire order -> M = 16,8,4,2,1)
__device__ __forceinline__ void half_ry_shear(u64 (&v)[32], const float* __restrict__ a) {
    u64 nt, sn;
    shear_consts(a[0], nt, sn); ry2_shear<16>(v, nt, sn);
    shear_consts(a[1], nt, sn); ry2_shear<8>(v, nt, sn);
    shear_consts(a[2], nt, sn); ry2_shear<4>(v, nt, sn);
    shear_consts(a[3], nt, sn); ry2_shear<2>(v, nt, sn);
    shear_consts(a[4], nt, sn); ry2_shear<1>(v, nt, sn);
}

__device__ __forceinline__ void half_ryrx(u64 (&v)[32], const float* __restrict__ a) {
    float c, s;
    __sincosf(0.5f * a[0], &s, &c); ry2<16>(v, c, s); rx2<16>(v, c, s);
    __sincosf(0.5f * a[1], &s, &c); ry2<8>(v, c, s);  rx2<8>(v, c, s);
    __sincosf(0.5f * a[2], &s, &c); ry2<4>(v, c, s);  rx2<4>(v, c, s);
    __sincosf(0.5f * a[3], &s, &c); ry2<2>(v, c, s);  rx2<2>(v, c, s);
    __sincosf(0.5f * a[4], &s, &c); ry2<1>(v, c, s);  rx2<1>(v, c, s);
}

// ===== Kernel 1: shared init (one warp per batch sample) =====
// Layout A: i = lane*32 + k ; Layout B: i = k*32 + lane.
__global__ void __launch_bounds__(32 * WPB)
qgen_init(const float* __restrict__ noise, int batch)
{
    __shared__ u64 tile[WPB][32 * 34];
    const unsigned lane = threadIdx.x & 31u;
    const unsigned w    = threadIdx.x >> 5;
    const unsigned b    = blockIdx.x * WPB + w;
    if ((int)b >= batch) return;

    u64 v[32];
    #pragma unroll
    for (int k = 0; k < 32; ++k) v[k] = 0ull;
    if (lane == 0) v[0] = pack2(1.0f, 0.0f);

    const float* nb = noise + (size_t)b * NQ;
    half_ryrx(v, nb + 5);              // layout A: wires 5..9
    transpose(v, tile[w], lane);       // -> layout B
    half_ryrx(v, nb + 0);              // wires 0..4

    u64* sp = g_snap + (size_t)b * 1024;
    #pragma unroll
    for (int k = 0; k < 32; ++k)
        sp[k * 32 + lane] = v[k];      // coalesced STG.64
}

// ===== Kernel 2: generator tails (one warp per (b, g)) =====
__global__ void __launch_bounds__(32 * WPB, 4)
qgen_tail(const float* __restrict__ qp,
          float* __restrict__ out, int batch)
{
    __shared__ u64 tile[WPB][32 * 34];
    const unsigned lane = threadIdx.x & 31u;
    const unsigned w    = threadIdx.x >> 5;
    const unsigned wid  = blockIdx.x * WPB + w;
    const unsigned b    = wid >> 2;          // 4 gens of one sample share a block
    const unsigned g    = wid & 3u;
    if ((int)b >= batch) return;
    u64* t = tile[w];

    const unsigned pL   = (__popc(lane & (lane >> 1)) & 1) ? 0xFFFFFFFFu : 0u;
    const unsigned sgnA = MK_CONST ^ pL ^ ((lane & 1u)        ? 0xFFFF0000u : 0u);
    const unsigned sgnB = MK_CONST ^ pL ^ (((lane >> 4) & 1u) ? 0xAAAAAAAAu : 0u);

    // load snapshot (layout B); coalesced, L1-shared across the block's 4 warps
    u64 v[32];
    const u64* sp = g_snap + (size_t)b * 1024;
    #pragma unroll
    for (int k = 0; k < 32; ++k)
        v[k] = sp[k * 32 + lane];

    const float* wg = qp + g * (QDEPTH * NQ);
    #pragma unroll
    for (int l = 0; l < QDEPTH; l += 2) {
        const float* w0 = wg + l * NQ;
        half_ry_shear(v, w0 + 0);      // layout B: wires 0..4
        transpose(v, t, lane);         // -> A
        half_ry_shear(v, w0 + 5);      // wires 5..9
        cz_apply(v, sgnA);
        const float* w1 = w0 + NQ;
        half_ry_shear(v, w1 + 5);      // layout A: wires 5..9
        transpose(v, t, lane);         // -> B
        half_ry_shear(v, w1 + 0);      // wires 0..4
        cz_apply(v, sgnB);
    }

    float e[10];
    e[0] = exv<16>(v); e[1] = exv<8>(v); e[2] = exv<4>(v);   // layout B: wires 0..4
    e[3] = exv<2>(v);  e[4] = exv<1>(v);
    transpose(v, t, lane);                                    // -> A
    e[5] = exv<16>(v); e[6] = exv<8>(v); e[7] = exv<4>(v);   // wires 5..9
    e[8] = exv<2>(v);  e[9] = exv<1>(v);

    #pragma unroll
    for (int q = 0; q < 10; ++q) {
        float a = e[q];
        #pragma unroll
        for (int o = 16; o; o >>= 1) a += __shfl_xor_sync(0xffffffffu, a, o);
        e[q] = a;
    }
    if (lane == 0) {
        float* ob = out + (size_t)b * (NGEN * NQ) + (size_t)g * NQ;
        #pragma unroll
        for (int q = 0; q < 10; ++q) ob[q] = e[q];
    }
}

extern "C" void kernel_launch(void* const* d_in, const int* in_sizes, int n_in,
                              void* d_out, int out_size) {
    const float* noise = (const float*)d_in[0];   // (BATCH, NQ) fp32
    const float* qp    = (const float*)d_in[1];   // (NGEN, QDEPTH, NQ) fp32
    float* out = (float*)d_out;                   // (BATCH, NGEN*NQ) fp32

    int batch = in_sizes[0] / NQ;
    if (batch > MAXB) batch = MAXB;

    int init_blocks = (batch + WPB - 1) / WPB;
    qgen_init<<<init_blocks, 32 * WPB>>>(noise, batch);

    int tail_warps  = batch * NGEN;
    int tail_blocks = (tail_warps + WPB - 1) / WPB;
    qgen_tail<<<tail_blocks, 32 * WPB>>>(qp, out, batch);
}